// round 6
// baseline (speedup 1.0000x reference)
#include <cuda_runtime.h>
#include <cstdint>

// Max-unpool scatter, deterministic last-index-wins (matches reference).
//
// Round-6: same 3-phase topology; fix coalescing of the ILP in Z and C.
//   Z: 4 uint4 stores/thread, BLOCK-STRIDED (warp-coalesced full lines)
//   S: atomicMax(scr[pos[i]], i+1), 8 atomics/thread, pos via __ldcs
//   C: 16 outputs/thread, block-strided vectors; scratch __ldcs (dead),
//      x __ldg (L2 reuse), out __stcs (write-once)

#define N_OUT_CONST 25690112  // 32*112*112*64

__device__ unsigned int g_winner[N_OUT_CONST];

// grid covers count4 = N_OUT/4 uint4 slots; each block owns 4*T consecutive
// slots; thread t stores slots base+t, base+t+T, base+t+2T, base+t+3T.
__global__ void zero_scratch_kernel(int count4) {
    const int T = blockDim.x;
    int base = blockIdx.x * (T * 4) + threadIdx.x;
    uint4* p = reinterpret_cast<uint4*>(g_winner);
    uint4 z = make_uint4(0u, 0u, 0u, 0u);
    // count4 is divisible by 4*T for our launch (handled by exact grid).
    p[base + 0 * T] = z;
    p[base + 1 * T] = z;
    p[base + 2 * T] = z;
    p[base + 3 * T] = z;
    (void)count4;
}

// n8 = n/8 threads, each loads 2 int4 of pos and issues 8 atomics.
__global__ void scatter_kernel(const int4* __restrict__ p4, int n8) {
    int t = blockIdx.x * blockDim.x + threadIdx.x;
    if (t >= n8) return;
    int4 a = __ldcs(&p4[2 * t + 0]);
    int4 b = __ldcs(&p4[2 * t + 1]);
    unsigned int base = (unsigned int)(t * 8);
    atomicMax(&g_winner[a.x], base + 1u);
    atomicMax(&g_winner[a.y], base + 2u);
    atomicMax(&g_winner[a.z], base + 3u);
    atomicMax(&g_winner[a.w], base + 4u);
    atomicMax(&g_winner[b.x], base + 5u);
    atomicMax(&g_winner[b.y], base + 6u);
    atomicMax(&g_winner[b.z], base + 7u);
    atomicMax(&g_winner[b.w], base + 8u);
}

// Each block owns 4*T uint4 slots (16*T outputs); thread t handles slots
// base+t+k*T for k=0..3 — all vector accesses warp-coalesced.
__global__ void compact_kernel(float* __restrict__ out,
                               const float* __restrict__ x) {
    const int T = blockDim.x;
    int base = blockIdx.x * (T * 4) + threadIdx.x;

    const uint4* __restrict__ sp = reinterpret_cast<const uint4*>(g_winner);
    float4* __restrict__ op = reinterpret_cast<float4*>(out);

    uint4 w[4];
#pragma unroll
    for (int k = 0; k < 4; k++) w[k] = __ldcs(&sp[base + k * T]);

    float4 o[4];
#pragma unroll
    for (int k = 0; k < 4; k++) {
        o[k].x = w[k].x ? __ldg(&x[w[k].x - 1u]) : 0.0f;
        o[k].y = w[k].y ? __ldg(&x[w[k].y - 1u]) : 0.0f;
        o[k].z = w[k].z ? __ldg(&x[w[k].z - 1u]) : 0.0f;
        o[k].w = w[k].w ? __ldg(&x[w[k].w - 1u]) : 0.0f;
    }

#pragma unroll
    for (int k = 0; k < 4; k++) __stcs(&op[base + k * T], o[k]);
}

extern "C" void kernel_launch(void* const* d_in, const int* in_sizes, int n_in,
                              void* d_out, int out_size) {
    const float* x = reinterpret_cast<const float*>(d_in[0]);
    const int* pos = reinterpret_cast<const int*>(d_in[1]);
    float* out     = reinterpret_cast<float*>(d_out);

    int n = in_sizes[0];             // 6,422,528 (divisible by 8)
    int n8 = n / 8;
    int count4 = out_size / 4;       // 6,422,528 uint4 slots

    const int T = 256;
    // count4 = 6,422,528 = 6272 * 1024 -> divisible by 4*T=1024: exact grid.
    const int ZG = count4 / (4 * T);
    const int SG = (n8 + T - 1) / T;
    const int CG = count4 / (4 * T);

    // Z: zero the winner scratch (heats it in L2 right before the atomics).
    zero_scratch_kernel<<<ZG, T>>>(count4);

    // S: deterministic last-index-wins via 32-bit atomicMax, 8/thread.
    scatter_kernel<<<SG, T>>>(reinterpret_cast<const int4*>(pos), n8);

    // C: gather winners' values, zero-fill empties, stream out, 16/thread.
    compact_kernel<<<CG, T>>>(out, x);
}